// round 13
// baseline (speedup 1.0000x reference)
#include <cuda_runtime.h>

#define BB 32
#define TT 200
#define TM 400
#define EE 256
#define HH 256
#define ENCX 512
#define DECX 1024
#define OUTX 80

#define SOFF (BB*TM*OUTX)
#define AOFF (SOFF + BB*TM)

#define NCTA 148
#define NTHR 512

#define XSTR 132   // [b][k] staging row stride: conflict-free LDS.128

// decoder smem layout (floats)
#define WS_OFF 0                   // 28*1616 = 45248 gate weights
#define XB0_OFF 45248              // 4224 staging buf 0
#define XB1_OFF 49472              // 4224 staging buf 1
#define V_OFF   53696              // 1024 attention v
#define GA_OFF  54720              // 896 gate accumulators
#define SMEM_F  55680
#define SMEM_BYTES (SMEM_F*4)      // 222720 B

// ---------------- device scratch ----------------
__device__ __align__(16) float g_enc_out[BB*TT*ENCX];
__device__ __align__(16) float g_proj[BB*TT*DECX];
__device__ __align__(16) float g_henc[2][2][HH*BB];
__device__ __align__(16) float g_cenc[2][HH*BB];
__device__ __align__(16) float g_hproj[BB*DECX];     // [b][d]
__device__ __align__(16) float g_scores[BB*TT];
__device__ __align__(16) float g_ctx[BB*ENCX];       // [b][e]
__device__ __align__(16) float g_hdec[2][BB*DECX];   // [p][b][k]
__device__ __align__(16) float g_cdec[DECX*BB];      // [u][b]

__device__ unsigned g_cnt8[8*32];
__device__ unsigned g_master = 0;
__device__ unsigned g_gen = 0;

__device__ __forceinline__ float sigf(float x) {
    return __fdividef(1.f, 1.f + __expf(-x));
}
__device__ __forceinline__ float tanhx(float x) {
    return 1.f - __fdividef(2.f, __expf(2.f * x) + 1.f);
}

__device__ __forceinline__ void gsync() {
    __syncthreads();
    if (threadIdx.x == 0) {
        __threadfence();
        const int grp = blockIdx.x & 7;
        const unsigned gsz = (grp < 4) ? 19u : 18u;
        unsigned g = g_gen;
        if (atomicAdd(&g_cnt8[grp*32], 1u) == gsz - 1u) {
            g_cnt8[grp*32] = 0u;
            if (atomicAdd(&g_master, 1u) == 7u) {
                g_master = 0u;
                __threadfence();
                atomicExch(&g_gen, g + 1u);
            }
        }
        while (((volatile unsigned*)&g_gen)[0] == g) { }
        __threadfence();
    }
    __syncthreads();
}

__global__ void __launch_bounds__(NTHR, 1) k_mega(
    const int* __restrict__ text, const float* __restrict__ melt,
    const float* __restrict__ emb,
    const float* __restrict__ efWih, const float* __restrict__ efWhh, const float* __restrict__ efb,
    const float* __restrict__ ebWih, const float* __restrict__ ebWhh, const float* __restrict__ ebb,
    const float* __restrict__ Ws, const float* __restrict__ bs, const float* __restrict__ v,
    const float* __restrict__ dWih, const float* __restrict__ dWhh, const float* __restrict__ db,
    const float* __restrict__ Wout, const float* __restrict__ bout,
    const float* __restrict__ Wstop, const float* __restrict__ bstop,
    float* __restrict__ out)
{
    extern __shared__ float sm[];
    const int cta  = blockIdx.x;
    const int tid  = threadIdx.x;
    const int w    = tid >> 5;
    const int lane = tid & 31;

    // ---------- zero states ----------
    {
        int gi = cta * NTHR + tid, gn = NCTA * NTHR;
        for (int j = gi; j < 2*2*HH*BB; j += gn) ((float*)g_henc)[j] = 0.f;
        for (int j = gi; j < 2*HH*BB;   j += gn) ((float*)g_cenc)[j] = 0.f;
        for (int j = gi; j < BB*DECX;   j += gn) g_hproj[j] = 0.f;
        for (int j = gi; j < 2*DECX*BB; j += gn) ((float*)g_hdec)[j] = 0.f;
        for (int j = gi; j < DECX*BB;   j += gn) g_cdec[j] = 0.f;
    }
    gsync();

    // ---------- encoder: 200 steps, CTAs 0..63 ----------
    for (int t = 0; t < TT; t++) {
        if (cta < 64) {
            const int dir  = cta >> 5;
            const int bxx  = cta & 31;
            const int part = w >> 3;
            const int wl   = w & 7;
            const int u    = bxx*8 + wl;
            const int p    = t & 1;
            const int tt   = dir ? (TT - 1 - t) : t;

            float* xs_e = sm;              // [256][33]
            float* hs_e = sm + 8448;       // [256][33]
            float* pa   = sm + 16896;      // [32][32]

            #pragma unroll
            for (int r2 = 0; r2 < 2; r2++) {
                int b2  = w*2 + r2;
                int tok = text[b2 * TT + tt];
                #pragma unroll
                for (int kq = 0; kq < 2; kq++) {
                    float4 v4 = *(const float4*)(emb + tok*EE + kq*128 + lane*4);
                    int kb = kq*128 + lane*4;
                    xs_e[(kb+0)*33+b2] = v4.x; xs_e[(kb+1)*33+b2] = v4.y;
                    xs_e[(kb+2)*33+b2] = v4.z; xs_e[(kb+3)*33+b2] = v4.w;
                }
            }
            {
                const float4* s4 = (const float4*)g_henc[dir][p];
                for (int i2 = tid; i2 < 2048; i2 += NTHR) {
                    float4 v4 = __ldcg(s4 + i2);
                    int k = i2 >> 3, b4 = (i2 & 7) * 4;
                    hs_e[k*33+b4+0] = v4.x; hs_e[k*33+b4+1] = v4.y;
                    hs_e[k*33+b4+2] = v4.z; hs_e[k*33+b4+3] = v4.w;
                }
            }
            __syncthreads();

            const float* bias = dir ? ebb : efb;
            float a0, a1, a2, a3;
            if (part) { a0 = a1 = a2 = a3 = 0.f; }
            else { a0 = bias[u]; a1 = bias[HH+u]; a2 = bias[2*HH+u]; a3 = bias[3*HH+u]; }
            const float* W  = part ? (dir ? ebWhh : efWhh) : (dir ? ebWih : efWih);
            const float* w0 = W + u*EE;
            const float* w1 = W + (HH+u)*EE;
            const float* w2 = W + (2*HH+u)*EE;
            const float* w3 = W + (3*HH+u)*EE;
            const float* xp = part ? hs_e : xs_e;

            #pragma unroll 8
            for (int k = 0; k < 256; k += 4) {
                float x0 = xp[(k+0)*33+lane], x1 = xp[(k+1)*33+lane];
                float x2 = xp[(k+2)*33+lane], x3 = xp[(k+3)*33+lane];
                float4 q;
                q = *(const float4*)(w0+k); a0 += q.x*x0+q.y*x1+q.z*x2+q.w*x3;
                q = *(const float4*)(w1+k); a1 += q.x*x0+q.y*x1+q.z*x2+q.w*x3;
                q = *(const float4*)(w2+k); a2 += q.x*x0+q.y*x1+q.z*x2+q.w*x3;
                q = *(const float4*)(w3+k); a3 += q.x*x0+q.y*x1+q.z*x2+q.w*x3;
            }
            if (part) {
                pa[(wl*4+0)*32+lane] = a0; pa[(wl*4+1)*32+lane] = a1;
                pa[(wl*4+2)*32+lane] = a2; pa[(wl*4+3)*32+lane] = a3;
            }
            __syncthreads();
            if (!part) {
                a0 += pa[(wl*4+0)*32+lane]; a1 += pa[(wl*4+1)*32+lane];
                a2 += pa[(wl*4+2)*32+lane]; a3 += pa[(wl*4+3)*32+lane];
                float cc = g_cenc[dir][u*32 + lane];
                float cn = sigf(a1) * cc + sigf(a0) * tanhx(a2);
                float hn = sigf(a3) * tanhx(cn);
                g_cenc[dir][u*32 + lane] = cn;
                g_henc[dir][1 - p][u*32 + lane] = hn;
                g_enc_out[(lane*TT + tt)*ENCX + dir*HH + u] = hn;
            }
        }
        gsync();
    }

    // ---------- proj_enc GEMM ----------
    {
        float* As = sm;           // [16][65]
        float* Bs = sm + 1040;    // [16][65]
        const int tx = tid & 15, ty2 = tid >> 4;
        for (int tl = cta; tl < 1600; tl += NCTA) {
            const int n0 = (tl & 15) * 64, m0 = (tl >> 4) * 64;
            float acc[2][4];
            #pragma unroll
            for (int i = 0; i < 2; i++)
                #pragma unroll
                for (int j = 0; j < 4; j++) acc[i][j] = 0.f;
            for (int k0 = 0; k0 < ENCX; k0 += 16) {
                if (tid < 256) {
                    int rr = tid >> 2, q = tid & 3;
                    float4 a4 = *(const float4*)(g_enc_out + (m0 + rr)*ENCX + k0 + q*4);
                    As[(q*4+0)*65+rr] = a4.x; As[(q*4+1)*65+rr] = a4.y;
                    As[(q*4+2)*65+rr] = a4.z; As[(q*4+3)*65+rr] = a4.w;
                } else {
                    int t2 = tid - 256;
                    int rr = t2 >> 2, q = t2 & 3;
                    float4 b4 = *(const float4*)(Ws + (n0 + rr)*(ENCX+DECX) + k0 + q*4);
                    Bs[(q*4+0)*65+rr] = b4.x; Bs[(q*4+1)*65+rr] = b4.y;
                    Bs[(q*4+2)*65+rr] = b4.z; Bs[(q*4+3)*65+rr] = b4.w;
                }
                __syncthreads();
                #pragma unroll
                for (int k = 0; k < 16; k++) {
                    float ar0 = As[k*65 + ty2*2 + 0];
                    float ar1 = As[k*65 + ty2*2 + 1];
                    float br[4];
                    #pragma unroll
                    for (int j = 0; j < 4; j++) br[j] = Bs[k*65 + tx*4 + j];
                    #pragma unroll
                    for (int j = 0; j < 4; j++) { acc[0][j] += ar0*br[j]; acc[1][j] += ar1*br[j]; }
                }
                __syncthreads();
            }
            #pragma unroll
            for (int i = 0; i < 2; i++)
                #pragma unroll
                for (int j = 0; j < 4; j++)
                    g_proj[(m0 + ty2*2 + i)*DECX + n0 + tx*4 + j] = acc[i][j] + bs[n0 + tx*4 + j];
        }
        __syncthreads();
    }

    // ---------- preload decoder gate weights + v ----------
    {
        for (int i = tid; i < 28*1616; i += NTHR) {
            int r = i / 1616, k = i - r*1616;
            int u = cta*7 + (r >> 2), g = r & 3;
            float val = 0.f;
            if (u < DECX)
                val = (k < 592) ? dWih[(g*DECX+u)*592 + k] : dWhh[(g*DECX+u)*DECX + (k-592)];
            sm[WS_OFF + i] = val;
        }
        for (int i = tid; i < DECX; i += NTHR) sm[V_OFF + i] = v[i];
        __syncthreads();
    }
    gsync();

    // ---------- decoder: 400 steps ----------
    float* xs0 = sm + XB0_OFF;
    float* xs1 = sm + XB1_OFF;
    const float* vs = sm + V_OFF;

    // persistent gate partial accumulators (act warps w<4): h@Whh part,
    // accumulated during D'(t-1), consumed in C'(t). h(-1)=0 -> init 0.
    float pacc[7];
    #pragma unroll
    for (int i = 0; i < 7; i++) pacc[i] = 0.f;

    for (int t = 0; t < TM; t++) {
        const int p = t & 1;

        // --- A: scores; 128 CTAs = (b, 50-s chunk); hproj cached in smem ---
        if (cta < 128) {
            const int b = cta >> 2, sc0 = (cta & 3) * 50;
            float* hp = xs0;
            for (int i = tid; i < DECX; i += NTHR) hp[i] = __ldcg(g_hproj + b*DECX + i);
            __syncthreads();
            for (int si = w; si < 50; si += 16) {
                const int s = sc0 + si;
                const float* pr = g_proj + (b*TT + s)*DECX;
                float acc = 0.f;
                #pragma unroll 8
                for (int d = lane; d < DECX; d += 32)
                    acc += vs[d] * tanhx(pr[d] + hp[d]);
                #pragma unroll
                for (int o = 16; o; o >>= 1) acc += __shfl_xor_sync(0xffffffffu, acc, o);
                if (lane == 0) g_scores[b*TT + s] = acc;
            }
        }
        gsync();

        // --- B: softmax + context, 128 CTAs (b x 4 e-chunks) ---
        if (cta < 128) {
            const int b = cta >> 2, ec = cta & 3;
            float* wb  = xs0;          // [200]
            float* red = xs0 + 256;    // [512]
            float* pc  = xs0 + 768;    // [512]
            float m = -1e30f;
            if (tid < TT) m = __ldcg(g_scores + b*TT + tid);
            red[tid] = m; __syncthreads();
            for (int st = 256; st > 0; st >>= 1) {
                if (tid < st) red[tid] = fmaxf(red[tid], red[tid + st]);
                __syncthreads();
            }
            m = red[0]; __syncthreads();
            float sum = 0.f;
            if (tid < TT) {
                float e2 = __expf(__ldcg(g_scores + b*TT + tid) - m);
                wb[tid] = e2; sum = e2;
            }
            red[tid] = sum; __syncthreads();
            for (int st = 256; st > 0; st >>= 1) {
                if (tid < st) red[tid] += red[tid + st];
                __syncthreads();
            }
            float inv = __fdividef(1.f, red[0]);
            __syncthreads();
            if (tid < TT) {
                float ww = wb[tid] * inv; wb[tid] = ww;
                if (ec == 0) out[AOFF + (b*TM + t)*TT + tid] = ww;
            }
            __syncthreads();
            const int el = tid & 127, sq = tid >> 7;
            const int e = ec*128 + el;
            float c = 0.f;
            #pragma unroll 2
            for (int s = sq*50; s < sq*50 + 50; s++)
                c += wb[s] * g_enc_out[(b*TT + s)*ENCX + e];
            pc[sq*128 + el] = c;
            __syncthreads();
            if (tid < 128)
                g_ctx[b*ENCX + ec*128 + tid] = pc[tid] + pc[128+tid] + pc[256+tid] + pc[384+tid];
        }
        gsync();

        // --- C': gates mel+ctx (K=592) + saved h-partial + LSTM ---
        {
            const float* wsb = sm + WS_OFF + (w*7)*1616;   // valid for w<4

            // stage chunk 0 (mel) -> xs0 (all warps)
            for (int i = tid; i < 640; i += NTHR) {
                int b2 = i / 20, q = i % 20;
                float4 mv = (t == 0) ? make_float4(0.f,0.f,0.f,0.f)
                          : *(const float4*)(melt + (b2*TM + (t-1))*OUTX + q*4);
                *(float4*)(xs0 + b2*XSTR + q*4) = mv;
            }
            __syncthreads();

            for (int c = 0; c <= 4; c++) {
                if (w >= 4 && c < 4) {
                    float* nxt = (c & 1) ? xs0 : xs1;   // buffer for chunk c+1
                    const float* src = g_ctx + c*128;
                    for (int i = (w-4)*32 + lane; i < 1024; i += 384) {
                        int b2 = i >> 5, q = i & 31;
                        float4 v4 = __ldcg((const float4*)(src + b2*ENCX + q*4));
                        *(float4*)(nxt + b2*XSTR + q*4) = v4;
                    }
                }
                if (w < 4) {
                    const float* cur = (c & 1) ? xs1 : xs0;
                    const int xo  = (c == 0) ? 0 : (OUTX + (c-1)*128);
                    const int len = (c == 0) ? OUTX : 128;
                    const float* xb = cur + lane*XSTR;
                    #pragma unroll 4
                    for (int k = 0; k < len; k += 4) {
                        float4 xv = *(const float4*)(xb + k);
                        #pragma unroll
                        for (int i = 0; i < 7; i++) {
                            float4 q = *(const float4*)(wsb + i*1616 + xo + k);
                            pacc[i] += q.x*xv.x + q.y*xv.y + q.z*xv.z + q.w*xv.w;
                        }
                    }
                }
                __syncthreads();
            }
            float* ga = sm + GA_OFF;
            if (w < 4) {
                #pragma unroll
                for (int i = 0; i < 7; i++) { ga[(w*7+i)*32 + lane] = pacc[i]; pacc[i] = 0.f; }
            }
            __syncthreads();
            if (tid < 224) {
                int u_l = tid >> 5, b2 = tid & 31;
                int uu = cta*7 + u_l;
                if (uu < DECX) {
                    float gi = ga[(u_l*4+0)*32+b2] + db[0*DECX+uu];
                    float gf = ga[(u_l*4+1)*32+b2] + db[1*DECX+uu];
                    float gg = ga[(u_l*4+2)*32+b2] + db[2*DECX+uu];
                    float go = ga[(u_l*4+3)*32+b2] + db[3*DECX+uu];
                    float cc = g_cdec[uu*32+b2];
                    float cn = sigf(gf)*cc + sigf(gi)*tanhx(gg);
                    float hn = sigf(go)*tanhx(cn);
                    g_cdec[uu*32+b2] = cn;
                    g_hdec[1-p][b2*DECX + uu] = hn;
                }
            }
        }
        gsync();

        // --- D': D-rows (hproj/mel/stop) + h@Whh partial for step t+1 ---
        {
            const int r0 = cta*8 + w*2;
            const int r1 = r0 + 1;
            const float* hsrc = g_hdec[1 - p];
            const float* wsb = sm + WS_OFF + (w*7)*1616;   // valid for w<4
            const float* wr0 = (r0 < DECX) ? (Ws + r0*(ENCX+DECX) + ENCX)
                             : (r0 < DECX+OUTX) ? (Wout + (r0-DECX)*DECX)
                             : Wstop;
            const float* wr1 = (r1 < DECX) ? (Ws + r1*(ENCX+DECX) + ENCX)
                             : (r1 < DECX+OUTX) ? (Wout + (r1-DECX)*DECX)
                             : Wstop;
            const bool dv = (r0 <= DECX + OUTX);
            float d0 = 0.f, d1 = 0.f;

            // stage chunk 0 (all warps)
            for (int i = tid; i < 1024; i += NTHR) {
                int b2 = i >> 5, q = i & 31;
                *(float4*)(xs0 + b2*XSTR + q*4) = __ldcg((const float4*)(hsrc + b2*DECX + q*4));
            }
            __syncthreads();

            for (int c = 0; c < 8; c++) {
                if (w >= 4 && c < 7) {
                    float* nxt = (c & 1) ? xs0 : xs1;
                    for (int i = (w-4)*32 + lane; i < 1024; i += 384) {
                        int b2 = i >> 5, q = i & 31;
                        *(float4*)(nxt + b2*XSTR + q*4) =
                            __ldcg((const float4*)(hsrc + b2*DECX + (c+1)*128 + q*4));
                    }
                }
                if (w < 4) {
                    const float* cur = (c & 1) ? xs1 : xs0;
                    const float* xb = cur + lane*XSTR;
                    const int ko = c*128;
                    #pragma unroll 4
                    for (int k = 0; k < 128; k += 4) {
                        float4 xv = *(const float4*)(xb + k);
                        if (dv) {
                            float4 q0 = *(const float4*)(wr0 + ko + k);
                            float4 q1 = *(const float4*)(wr1 + ko + k);
                            d0 += q0.x*xv.x + q0.y*xv.y + q0.z*xv.z + q0.w*xv.w;
                            d1 += q1.x*xv.x + q1.y*xv.y + q1.z*xv.z + q1.w*xv.w;
                        }
                        #pragma unroll
                        for (int i = 0; i < 7; i++) {
                            float4 q = *(const float4*)(wsb + i*1616 + 592 + ko + k);
                            pacc[i] += q.x*xv.x + q.y*xv.y + q.z*xv.z + q.w*xv.w;
                        }
                    }
                }
                __syncthreads();
            }
            if (w < 4) {
                if (r0 < DECX) g_hproj[lane*DECX + r0] = d0;
                else if (r0 < DECX+OUTX) out[(lane*TM + t)*OUTX + (r0-DECX)] = d0 + bout[r0-DECX];
                else if (r0 == DECX+OUTX) out[SOFF + lane*TM + t] = sigf(d0 + bstop[0]);
                if (r1 < DECX) g_hproj[lane*DECX + r1] = d1;
                else if (r1 < DECX+OUTX) out[(lane*TM + t)*OUTX + (r1-DECX)] = d1 + bout[r1-DECX];
                else if (r1 == DECX+OUTX) out[SOFF + lane*TM + t] = sigf(d1 + bstop[0]);
            }
        }
        gsync();
    }
}

extern "C" void kernel_launch(void* const* d_in, const int* in_sizes, int n_in,
                              void* d_out, int out_size)
{
    const int*   text  = (const int*)d_in[0];
    const float* melt  = (const float*)d_in[1];
    const float* emb   = (const float*)d_in[2];
    const float* efWih = (const float*)d_in[3];
    const float* efWhh = (const float*)d_in[4];
    const float* efb   = (const float*)d_in[5];
    const float* ebWih = (const float*)d_in[6];
    const float* ebWhh = (const float*)d_in[7];
    const float* ebb   = (const float*)d_in[8];
    const float* Ws    = (const float*)d_in[9];
    const float* bs    = (const float*)d_in[10];
    const float* v     = (const float*)d_in[11];
    const float* dWih  = (const float*)d_in[12];
    const float* dWhh  = (const float*)d_in[13];
    const float* db    = (const float*)d_in[14];
    const float* Wout  = (const float*)d_in[15];
    const float* bout  = (const float*)d_in[16];
    const float* Wstop = (const float*)d_in[17];
    const float* bstop = (const float*)d_in[18];
    float* out = (float*)d_out;

    static int smem_set = 0;
    if (!smem_set) {
        cudaFuncSetAttribute(k_mega, cudaFuncAttributeMaxDynamicSharedMemorySize, SMEM_BYTES);
        smem_set = 1;
    }
    k_mega<<<NCTA, NTHR, SMEM_BYTES>>>(text, melt, emb, efWih, efWhh, efb,
                                       ebWih, ebWhh, ebb, Ws, bs, v,
                                       dWih, dWhh, db, Wout, bout, Wstop, bstop, out);
}

// round 16
// speedup vs baseline: 1.0642x; 1.0642x over previous
#include <cuda_runtime.h>

#define BB 32
#define TT 200
#define TM 400
#define EE 256
#define HH 256
#define ENCX 512
#define DECX 1024
#define OUTX 80

#define SOFF (BB*TM*OUTX)
#define AOFF (SOFF + BB*TM)

#define NCTA 148
#define NTHR 512

#define XSTR 132   // [b][k] staging row stride: conflict-free LDS.128

// decoder smem layout (floats)
#define WS_OFF 0                   // 28*1616 = 45248 gate weights
#define XB0_OFF 45248              // 4224 staging buf 0
#define XB1_OFF 49472              // 4224 staging buf 1
#define V_OFF   53696              // 1024 attention v
#define GA_OFF  54720              // 896 gate accumulators
#define SMEM_F  55680
#define SMEM_BYTES (SMEM_F*4)      // 222720 B

// ---------------- device scratch ----------------
__device__ __align__(16) float g_enc_out[BB*TT*ENCX];
__device__ __align__(16) float g_proj[BB*TT*DECX];
__device__ __align__(16) float g_henc[2][2][HH*BB];
__device__ __align__(16) float g_cenc[2][HH*BB];
__device__ __align__(16) float g_hproj[BB*DECX];     // [b][d]
__device__ __align__(16) float g_scores[BB*TT];
__device__ __align__(16) float g_ctx[BB*ENCX];       // [b][e]
__device__ __align__(16) float g_hdec[2][BB*DECX];   // [p][b][k]
__device__ __align__(16) float g_cdec[DECX*BB];      // [u][b]

__device__ unsigned g_cnt8[8*32];
__device__ unsigned g_master = 0;
__device__ unsigned g_gen = 0;

__device__ __forceinline__ float sigf(float x) {
    return __fdividef(1.f, 1.f + __expf(-x));
}
__device__ __forceinline__ float tanhx(float x) {
    return 1.f - __fdividef(2.f, __expf(2.f * x) + 1.f);
}

__device__ __forceinline__ void gsync() {
    __syncthreads();
    if (threadIdx.x == 0) {
        __threadfence();
        const int grp = blockIdx.x & 7;
        const unsigned gsz = (grp < 4) ? 19u : 18u;
        unsigned g = g_gen;
        if (atomicAdd(&g_cnt8[grp*32], 1u) == gsz - 1u) {
            g_cnt8[grp*32] = 0u;
            if (atomicAdd(&g_master, 1u) == 7u) {
                g_master = 0u;
                __threadfence();
                atomicExch(&g_gen, g + 1u);
            }
        }
        while (((volatile unsigned*)&g_gen)[0] == g) { }
        __threadfence();
    }
    __syncthreads();
}

// NR gate rows against x chunk in smem ([b][k], stride XSTR)
template<int NR>
__device__ __forceinline__ void gemv_rows(const float* __restrict__ wsb,
                                          const float* __restrict__ xb,
                                          int xo, int len, float* acc) {
    #pragma unroll 4
    for (int k = 0; k < len; k += 4) {
        float4 xv = *(const float4*)(xb + k);
        #pragma unroll
        for (int i = 0; i < NR; i++) {
            float4 q = *(const float4*)(wsb + i*1616 + xo + k);
            acc[i] += q.x*xv.x + q.y*xv.y + q.z*xv.z + q.w*xv.w;
        }
    }
}

__global__ void __launch_bounds__(NTHR, 1) k_mega(
    const int* __restrict__ text, const float* __restrict__ melt,
    const float* __restrict__ emb,
    const float* __restrict__ efWih, const float* __restrict__ efWhh, const float* __restrict__ efb,
    const float* __restrict__ ebWih, const float* __restrict__ ebWhh, const float* __restrict__ ebb,
    const float* __restrict__ Ws, const float* __restrict__ bs, const float* __restrict__ v,
    const float* __restrict__ dWih, const float* __restrict__ dWhh, const float* __restrict__ db,
    const float* __restrict__ Wout, const float* __restrict__ bout,
    const float* __restrict__ Wstop, const float* __restrict__ bstop,
    float* __restrict__ out)
{
    extern __shared__ float sm[];
    const int cta  = blockIdx.x;
    const int tid  = threadIdx.x;
    const int w    = tid >> 5;
    const int lane = tid & 31;

    // ---------- zero states ----------
    {
        int gi = cta * NTHR + tid, gn = NCTA * NTHR;
        for (int j = gi; j < 2*2*HH*BB; j += gn) ((float*)g_henc)[j] = 0.f;
        for (int j = gi; j < 2*HH*BB;   j += gn) ((float*)g_cenc)[j] = 0.f;
        for (int j = gi; j < BB*DECX;   j += gn) g_hproj[j] = 0.f;
        for (int j = gi; j < 2*DECX*BB; j += gn) ((float*)g_hdec)[j] = 0.f;
        for (int j = gi; j < DECX*BB;   j += gn) g_cdec[j] = 0.f;
    }
    gsync();

    // ---------- encoder: 200 steps, CTAs 0..63 ----------
    for (int t = 0; t < TT; t++) {
        if (cta < 64) {
            const int dir  = cta >> 5;
            const int bxx  = cta & 31;
            const int part = w >> 3;
            const int wl   = w & 7;
            const int u    = bxx*8 + wl;
            const int p    = t & 1;
            const int tt   = dir ? (TT - 1 - t) : t;

            float* xs_e = sm;              // [256][33]
            float* hs_e = sm + 8448;       // [256][33]
            float* pa   = sm + 16896;      // [32][32]

            #pragma unroll
            for (int r2 = 0; r2 < 2; r2++) {
                int b2  = w*2 + r2;
                int tok = text[b2 * TT + tt];
                #pragma unroll
                for (int kq = 0; kq < 2; kq++) {
                    float4 v4 = *(const float4*)(emb + tok*EE + kq*128 + lane*4);
                    int kb = kq*128 + lane*4;
                    xs_e[(kb+0)*33+b2] = v4.x; xs_e[(kb+1)*33+b2] = v4.y;
                    xs_e[(kb+2)*33+b2] = v4.z; xs_e[(kb+3)*33+b2] = v4.w;
                }
            }
            {
                const float4* s4 = (const float4*)g_henc[dir][p];
                for (int i2 = tid; i2 < 2048; i2 += NTHR) {
                    float4 v4 = __ldcg(s4 + i2);
                    int k = i2 >> 3, b4 = (i2 & 7) * 4;
                    hs_e[k*33+b4+0] = v4.x; hs_e[k*33+b4+1] = v4.y;
                    hs_e[k*33+b4+2] = v4.z; hs_e[k*33+b4+3] = v4.w;
                }
            }
            __syncthreads();

            const float* bias = dir ? ebb : efb;
            float a0, a1, a2, a3;
            if (part) { a0 = a1 = a2 = a3 = 0.f; }
            else { a0 = bias[u]; a1 = bias[HH+u]; a2 = bias[2*HH+u]; a3 = bias[3*HH+u]; }
            const float* W  = part ? (dir ? ebWhh : efWhh) : (dir ? ebWih : efWih);
            const float* w0 = W + u*EE;
            const float* w1 = W + (HH+u)*EE;
            const float* w2 = W + (2*HH+u)*EE;
            const float* w3 = W + (3*HH+u)*EE;
            const float* xp = part ? hs_e : xs_e;

            #pragma unroll 8
            for (int k = 0; k < 256; k += 4) {
                float x0 = xp[(k+0)*33+lane], x1 = xp[(k+1)*33+lane];
                float x2 = xp[(k+2)*33+lane], x3 = xp[(k+3)*33+lane];
                float4 q;
                q = *(const float4*)(w0+k); a0 += q.x*x0+q.y*x1+q.z*x2+q.w*x3;
                q = *(const float4*)(w1+k); a1 += q.x*x0+q.y*x1+q.z*x2+q.w*x3;
                q = *(const float4*)(w2+k); a2 += q.x*x0+q.y*x1+q.z*x2+q.w*x3;
                q = *(const float4*)(w3+k); a3 += q.x*x0+q.y*x1+q.z*x2+q.w*x3;
            }
            if (part) {
                pa[(wl*4+0)*32+lane] = a0; pa[(wl*4+1)*32+lane] = a1;
                pa[(wl*4+2)*32+lane] = a2; pa[(wl*4+3)*32+lane] = a3;
            }
            __syncthreads();
            if (!part) {
                a0 += pa[(wl*4+0)*32+lane]; a1 += pa[(wl*4+1)*32+lane];
                a2 += pa[(wl*4+2)*32+lane]; a3 += pa[(wl*4+3)*32+lane];
                float cc = g_cenc[dir][u*32 + lane];
                float cn = sigf(a1) * cc + sigf(a0) * tanhx(a2);
                float hn = sigf(a3) * tanhx(cn);
                g_cenc[dir][u*32 + lane] = cn;
                g_henc[dir][1 - p][u*32 + lane] = hn;
                g_enc_out[(lane*TT + tt)*ENCX + dir*HH + u] = hn;
            }
        }
        gsync();
    }

    // ---------- proj_enc GEMM ----------
    {
        float* As = sm;           // [16][65]
        float* Bs = sm + 1040;    // [16][65]
        const int tx = tid & 15, ty2 = tid >> 4;
        for (int tl = cta; tl < 1600; tl += NCTA) {
            const int n0 = (tl & 15) * 64, m0 = (tl >> 4) * 64;
            float acc[2][4];
            #pragma unroll
            for (int i = 0; i < 2; i++)
                #pragma unroll
                for (int j = 0; j < 4; j++) acc[i][j] = 0.f;
            for (int k0 = 0; k0 < ENCX; k0 += 16) {
                if (tid < 256) {
                    int rr = tid >> 2, q = tid & 3;
                    float4 a4 = *(const float4*)(g_enc_out + (m0 + rr)*ENCX + k0 + q*4);
                    As[(q*4+0)*65+rr] = a4.x; As[(q*4+1)*65+rr] = a4.y;
                    As[(q*4+2)*65+rr] = a4.z; As[(q*4+3)*65+rr] = a4.w;
                } else {
                    int t2 = tid - 256;
                    int rr = t2 >> 2, q = t2 & 3;
                    float4 b4 = *(const float4*)(Ws + (n0 + rr)*(ENCX+DECX) + k0 + q*4);
                    Bs[(q*4+0)*65+rr] = b4.x; Bs[(q*4+1)*65+rr] = b4.y;
                    Bs[(q*4+2)*65+rr] = b4.z; Bs[(q*4+3)*65+rr] = b4.w;
                }
                __syncthreads();
                #pragma unroll
                for (int k = 0; k < 16; k++) {
                    float ar0 = As[k*65 + ty2*2 + 0];
                    float ar1 = As[k*65 + ty2*2 + 1];
                    float br[4];
                    #pragma unroll
                    for (int j = 0; j < 4; j++) br[j] = Bs[k*65 + tx*4 + j];
                    #pragma unroll
                    for (int j = 0; j < 4; j++) { acc[0][j] += ar0*br[j]; acc[1][j] += ar1*br[j]; }
                }
                __syncthreads();
            }
            #pragma unroll
            for (int i = 0; i < 2; i++)
                #pragma unroll
                for (int j = 0; j < 4; j++)
                    g_proj[(m0 + ty2*2 + i)*DECX + n0 + tx*4 + j] = acc[i][j] + bs[n0 + tx*4 + j];
        }
        __syncthreads();
    }

    // ---------- preload decoder gate weights + v ----------
    {
        for (int i = tid; i < 28*1616; i += NTHR) {
            int r = i / 1616, k = i - r*1616;
            int u = cta*7 + (r >> 2), g = r & 3;
            float val = 0.f;
            if (u < DECX)
                val = (k < 592) ? dWih[(g*DECX+u)*592 + k] : dWhh[(g*DECX+u)*DECX + (k-592)];
            sm[WS_OFF + i] = val;
        }
        for (int i = tid; i < DECX; i += NTHR) sm[V_OFF + i] = v[i];
        __syncthreads();
    }
    gsync();

    // ---------- decoder: 400 steps ----------
    float* xs0 = sm + XB0_OFF;
    float* xs1 = sm + XB1_OFF;
    const float* vs = sm + V_OFF;

    for (int t = 0; t < TM; t++) {
        const int p = t & 1;

        // --- A: scores; 128 CTAs = (b, 50-s chunk); hproj cached in smem ---
        if (cta < 128) {
            const int b = cta >> 2, sc0 = (cta & 3) * 50;
            float* hp = xs0;
            for (int i = tid; i < DECX; i += NTHR) hp[i] = __ldcg(g_hproj + b*DECX + i);
            __syncthreads();
            for (int si = w; si < 50; si += 16) {
                const int s = sc0 + si;
                const float* pr = g_proj + (b*TT + s)*DECX;
                float acc = 0.f;
                #pragma unroll 8
                for (int d = lane; d < DECX; d += 32)
                    acc += vs[d] * tanhx(pr[d] + hp[d]);
                #pragma unroll
                for (int o = 16; o; o >>= 1) acc += __shfl_xor_sync(0xffffffffu, acc, o);
                if (lane == 0) g_scores[b*TT + s] = acc;
            }
        }
        gsync();

        // --- B: softmax + context, 128 CTAs (b x 4 e-chunks); shuffle reductions ---
        if (cta < 128) {
            const int b = cta >> 2, ec = cta & 3;
            float* wb  = xs0;          // [200]
            float* red = xs0 + 256;    // [16]
            float* pc  = xs0 + 288;    // [512]
            float sc = (tid < TT) ? __ldcg(g_scores + b*TT + tid) : -1e30f;

            float m = sc;
            #pragma unroll
            for (int o = 16; o; o >>= 1) m = fmaxf(m, __shfl_xor_sync(0xffffffffu, m, o));
            if (lane == 0) red[w] = m;
            __syncthreads();
            m = red[0];
            #pragma unroll
            for (int i = 1; i < 16; i++) m = fmaxf(m, red[i]);
            __syncthreads();

            float e2 = (tid < TT) ? __expf(sc - m) : 0.f;
            float sum = e2;
            #pragma unroll
            for (int o = 16; o; o >>= 1) sum += __shfl_xor_sync(0xffffffffu, sum, o);
            if (lane == 0) red[w] = sum;
            __syncthreads();
            sum = red[0];
            #pragma unroll
            for (int i = 1; i < 16; i++) sum += red[i];

            float inv = __fdividef(1.f, sum);
            if (tid < TT) {
                float ww = e2 * inv; wb[tid] = ww;
                if (ec == 0) out[AOFF + (b*TM + t)*TT + tid] = ww;
            }
            __syncthreads();
            const int el = tid & 127, sq = tid >> 7;
            const int e = ec*128 + el;
            float c = 0.f;
            #pragma unroll 2
            for (int s = sq*50; s < sq*50 + 50; s++)
                c += wb[s] * g_enc_out[(b*TT + s)*ENCX + e];
            pc[sq*128 + el] = c;
            __syncthreads();
            if (tid < 128)
                g_ctx[b*ENCX + ec*128 + tid] = pc[tid] + pc[128+tid] + pc[256+tid] + pc[384+tid];
        }
        gsync();

        // --- C: gates GEMM + LSTM; 8 act warps (2/SMSP, 7 rows/SMSP), 8 staging ---
        {
            const int nr = (w < 4) ? 4 : 3;
            const int rb = (w < 4) ? w*4 : 16 + (w-4)*3;   // row base (w<8)
            const float* wsb = sm + WS_OFF + rb*1616;
            float acc[4] = {0.f, 0.f, 0.f, 0.f};

            // stage chunk 0 (mel) -> xs0 (all warps)
            for (int i = tid; i < 640; i += NTHR) {
                int b2 = i / 20, q = i % 20;
                float4 mv = (t == 0) ? make_float4(0.f,0.f,0.f,0.f)
                          : *(const float4*)(melt + (b2*TM + (t-1))*OUTX + q*4);
                *(float4*)(xs0 + b2*XSTR + q*4) = mv;
            }
            __syncthreads();

            for (int c = 0; c <= 12; c++) {
                if (w >= 8 && c < 12) {
                    float* nxt = (c & 1) ? xs0 : xs1;   // buffer for chunk c+1
                    const float* src = (c < 4) ? (g_ctx + c*128)
                                               : (g_hdec[p] + (c-4)*128);
                    const int stride = (c < 4) ? ENCX : DECX;
                    for (int i = (w-8)*32 + lane; i < 1024; i += 256) {
                        int b2 = i >> 5, q = i & 31;
                        float4 v4 = __ldcg((const float4*)(src + b2*stride + q*4));
                        *(float4*)(nxt + b2*XSTR + q*4) = v4;
                    }
                }
                if (w < 8) {
                    const float* cur = (c & 1) ? xs1 : xs0;
                    const int xo  = (c == 0) ? 0 : (OUTX + (c-1)*128);
                    const int len = (c == 0) ? OUTX : 128;
                    const float* xb = cur + lane*XSTR;
                    if (w < 4) gemv_rows<4>(wsb, xb, xo, len, acc);
                    else       gemv_rows<3>(wsb, xb, xo, len, acc);
                }
                __syncthreads();
            }
            float* ga = sm + GA_OFF;
            if (w < 8) {
                for (int i = 0; i < nr; i++) ga[(rb+i)*32 + lane] = acc[i];
            }
            __syncthreads();
            if (tid < 224) {
                int u_l = tid >> 5, b2 = tid & 31;
                int uu = cta*7 + u_l;
                if (uu < DECX) {
                    float gi = ga[(u_l*4+0)*32+b2] + db[0*DECX+uu];
                    float gf = ga[(u_l*4+1)*32+b2] + db[1*DECX+uu];
                    float gg = ga[(u_l*4+2)*32+b2] + db[2*DECX+uu];
                    float go = ga[(u_l*4+3)*32+b2] + db[3*DECX+uu];
                    float cc = g_cdec[uu*32+b2];
                    float cn = sigf(gf)*cc + sigf(gi)*tanhx(gg);
                    float hn = sigf(go)*tanhx(cn);
                    g_cdec[uu*32+b2] = cn;
                    g_hdec[1-p][b2*DECX + uu] = hn;
                }
            }
        }
        gsync();

        // --- D: hproj / mel / stop; 8 act warps x 1 row, 8 staging warps ---
        {
            const int r = cta*8 + w;   // valid for w<8
            const float* hsrc = g_hdec[1 - p];
            const float* wr = (r < DECX) ? (Ws + r*(ENCX+DECX) + ENCX)
                            : (r < DECX+OUTX) ? (Wout + (r-DECX)*DECX)
                            : Wstop;
            const bool dv = (w < 8) && (r <= DECX + OUTX);
            float d0 = 0.f;

            // stage chunk 0 (all warps)
            for (int i = tid; i < 1024; i += NTHR) {
                int b2 = i >> 5, q = i & 31;
                *(float4*)(xs0 + b2*XSTR + q*4) = __ldcg((const float4*)(hsrc + b2*DECX + q*4));
            }
            __syncthreads();

            for (int c = 0; c < 8; c++) {
                if (w >= 8 && c < 7) {
                    float* nxt = (c & 1) ? xs0 : xs1;
                    for (int i = (w-8)*32 + lane; i < 1024; i += 256) {
                        int b2 = i >> 5, q = i & 31;
                        *(float4*)(nxt + b2*XSTR + q*4) =
                            __ldcg((const float4*)(hsrc + b2*DECX + (c+1)*128 + q*4));
                    }
                }
                if (dv) {
                    const float* cur = (c & 1) ? xs1 : xs0;
                    const float* xb = cur + lane*XSTR;
                    const int ko = c*128;
                    #pragma unroll 8
                    for (int k = 0; k < 128; k += 4) {
                        float4 xv = *(const float4*)(xb + k);
                        float4 q0 = *(const float4*)(wr + ko + k);
                        d0 += q0.x*xv.x + q0.y*xv.y + q0.z*xv.z + q0.w*xv.w;
                    }
                }
                __syncthreads();
            }
            if (dv) {
                if (r < DECX) g_hproj[lane*DECX + r] = d0;
                else if (r < DECX+OUTX) out[(lane*TM + t)*OUTX + (r-DECX)] = d0 + bout[r-DECX];
                else out[SOFF + lane*TM + t] = sigf(d0 + bstop[0]);
            }
        }
        gsync();
    }
}

extern "C" void kernel_launch(void* const* d_in, const int* in_sizes, int n_in,
                              void* d_out, int out_size)
{
    const int*   text  = (const int*)d_in[0];
    const float* melt  = (const float*)d_in[1];
    const float* emb   = (const float*)d_in[2];
    const float* efWih = (const float*)d_in[3];
    const float* efWhh = (const float*)d_in[4];
    const float* efb   = (const float*)d_in[5];
    const float* ebWih = (const float*)d_in[6];
    const float* ebWhh = (const float*)d_in[7];
    const float* ebb   = (const float*)d_in[8];
    const float* Ws    = (const float*)d_in[9];
    const float* bs    = (const float*)d_in[10];
    const float* v     = (const float*)d_in[11];
    const float* dWih  = (const float*)d_in[12];
    const float* dWhh  = (const float*)d_in[13];
    const float* db    = (const float*)d_in[14];
    const float* Wout  = (const float*)d_in[15];
    const float* bout  = (const float*)d_in[16];
    const float* Wstop = (const float*)d_in[17];
    const float* bstop = (const float*)d_in[18];
    float* out = (float*)d_out;

    static int smem_set = 0;
    if (!smem_set) {
        cudaFuncSetAttribute(k_mega, cudaFuncAttributeMaxDynamicSharedMemorySize, SMEM_BYTES);
        smem_set = 1;
    }
    k_mega<<<NCTA, NTHR, SMEM_BYTES>>>(text, melt, emb, efWih, efWhh, efb,
                                       ebWih, ebWhh, ebb, Ws, bs, v,
                                       dWih, dWhh, db, Wout, bout, Wstop, bstop, out);
}

// round 17
// speedup vs baseline: 1.1243x; 1.0565x over previous
#include <cuda_runtime.h>

#define BB 32
#define TT 200
#define TM 400
#define EE 256
#define HH 256
#define ENCX 512
#define DECX 1024
#define OUTX 80

#define SOFF (BB*TM*OUTX)
#define AOFF (SOFF + BB*TM)

#define NCTA 148
#define NTHR 1024

#define XSTR 132   // [b][k] staging row stride: conflict-free LDS.128

// decoder smem layout (floats)
#define WS_OFF 0                   // 28*1616 = 45248 gate weights
#define XB0_OFF 45248              // 4224 staging buf 0
#define XB1_OFF 49472              // 4224 staging buf 1
#define V_OFF   53696              // 1024 attention v
#define GA_OFF  54720              // 896 gate accumulators
#define SMEM_F  55680
#define SMEM_BYTES (SMEM_F*4)      // 222720 B

// encoder smem layout (floats) — lives before decoder preload overwrites it
#define EW_OFF  0                  // 32 rows x 512 = 16384 enc weights
#define EXS_OFF 16384              // [256][33] x staging
#define EHS_OFF 24832              // [256][33] h staging
#define EPA_OFF 33280              // 4 x 32 x 32 partials
#define EGA_OFF 37376              // 32 x 32 gates

// ---------------- device scratch ----------------
__device__ __align__(16) float g_enc_out[BB*TT*ENCX];
__device__ __align__(16) float g_proj[BB*TT*DECX];
__device__ __align__(16) float g_henc[2][2][HH*BB];
__device__ __align__(16) float g_cenc[2][HH*BB];
__device__ __align__(16) float g_hproj[BB*DECX];     // [b][d]
__device__ __align__(16) float g_scores[BB*TT];
__device__ __align__(16) float g_ctx[BB*ENCX];       // [b][e]
__device__ __align__(16) float g_hdec[2][BB*DECX];   // [p][b][k]
__device__ __align__(16) float g_cdec[DECX*BB];      // [u][b]

__device__ unsigned g_cnt8[8*32];
__device__ unsigned g_master = 0;
__device__ unsigned g_gen = 0;
__device__ unsigned e_cnt[2*32];
__device__ unsigned e_gen[2*32];

__device__ __forceinline__ float sigf(float x) {
    return __fdividef(1.f, 1.f + __expf(-x));
}
__device__ __forceinline__ float tanhx(float x) {
    return 1.f - __fdividef(2.f, __expf(2.f * x) + 1.f);
}

__device__ __forceinline__ void gsync() {
    __syncthreads();
    if (threadIdx.x == 0) {
        __threadfence();
        const int grp = blockIdx.x & 7;
        const unsigned gsz = (grp < 4) ? 19u : 18u;
        unsigned g = g_gen;
        if (atomicAdd(&g_cnt8[grp*32], 1u) == gsz - 1u) {
            g_cnt8[grp*32] = 0u;
            if (atomicAdd(&g_master, 1u) == 7u) {
                g_master = 0u;
                __threadfence();
                atomicExch(&g_gen, g + 1u);
            }
        }
        while (((volatile unsigned*)&g_gen)[0] == g) { }
        __threadfence();
    }
    __syncthreads();
}

// 32-CTA barrier among one encoder direction
__device__ __forceinline__ void esync(int dir) {
    __syncthreads();
    if (threadIdx.x == 0) {
        __threadfence();
        unsigned g = e_gen[dir*32];
        if (atomicAdd(&e_cnt[dir*32], 1u) == 31u) {
            e_cnt[dir*32] = 0u;
            __threadfence();
            atomicExch(&e_gen[dir*32], g + 1u);
        } else {
            while (((volatile unsigned*)&e_gen[dir*32])[0] == g) { }
        }
        __threadfence();
    }
    __syncthreads();
}

// NR gate rows against x chunk in smem ([b][k], stride XSTR)
template<int NR>
__device__ __forceinline__ void gemv_rows(const float* __restrict__ wsb,
                                          const float* __restrict__ xb,
                                          int xo, int len, float* acc) {
    #pragma unroll 4
    for (int k = 0; k < len; k += 4) {
        float4 xv = *(const float4*)(xb + k);
        #pragma unroll
        for (int i = 0; i < NR; i++) {
            float4 q = *(const float4*)(wsb + i*1616 + xo + k);
            acc[i] += q.x*xv.x + q.y*xv.y + q.z*xv.z + q.w*xv.w;
        }
    }
}

__global__ void __launch_bounds__(NTHR, 1) k_mega(
    const int* __restrict__ text, const float* __restrict__ melt,
    const float* __restrict__ emb,
    const float* __restrict__ efWih, const float* __restrict__ efWhh, const float* __restrict__ efb,
    const float* __restrict__ ebWih, const float* __restrict__ ebWhh, const float* __restrict__ ebb,
    const float* __restrict__ Ws, const float* __restrict__ bs, const float* __restrict__ v,
    const float* __restrict__ dWih, const float* __restrict__ dWhh, const float* __restrict__ db,
    const float* __restrict__ Wout, const float* __restrict__ bout,
    const float* __restrict__ Wstop, const float* __restrict__ bstop,
    float* __restrict__ out)
{
    extern __shared__ float sm[];
    const int cta  = blockIdx.x;
    const int tid  = threadIdx.x;
    const int w    = tid >> 5;
    const int lane = tid & 31;

    // ---------- zero states ----------
    {
        int gi = cta * NTHR + tid, gn = NCTA * NTHR;
        for (int j = gi; j < 2*2*HH*BB; j += gn) ((float*)g_henc)[j] = 0.f;
        for (int j = gi; j < 2*HH*BB;   j += gn) ((float*)g_cenc)[j] = 0.f;
        for (int j = gi; j < BB*DECX;   j += gn) g_hproj[j] = 0.f;
        for (int j = gi; j < 2*DECX*BB; j += gn) ((float*)g_hdec)[j] = 0.f;
        for (int j = gi; j < DECX*BB;   j += gn) g_cdec[j] = 0.f;
    }
    gsync();

    // ---------- encoder: 200 steps, CTAs 0..63, weights in smem ----------
    if (cta < 64) {
        const int dir = cta >> 5;
        const int bxx = cta & 31;
        const float* Wih  = dir ? ebWih : efWih;
        const float* Whh  = dir ? ebWhh : efWhh;
        const float* bias = dir ? ebb   : efb;

        // preload this CTA's 32 weight rows: row r=g*8+ui -> [Wih row | Whh row]
        for (int i = tid; i < 32*512; i += NTHR) {
            int r = i >> 9, k = i & 511;
            int g = r >> 3, ui = r & 7;
            int u = bxx*8 + ui;
            float val = (k < 256) ? Wih[(g*HH+u)*EE + k] : Whh[(g*HH+u)*HH + (k-256)];
            sm[EW_OFF + i] = val;
        }
        __syncthreads();

        float* xs_e = sm + EXS_OFF;   // [256][33]
        float* hs_e = sm + EHS_OFF;   // [256][33]
        float* pa   = sm + EPA_OFF;   // [4][32][32]
        float* ga   = sm + EGA_OFF;   // [32][32]

        const int u_w  = w & 7;           // u within CTA's 8
        const int part = (w >> 3) & 1;    // 0: x@Wih, 1: h@Whh
        const int qh   = w >> 4;          // k quarter-half within part
        const int pq   = part*2 + qh;

        for (int t = 0; t < TT; t++) {
            const int p  = t & 1;
            const int tt = dir ? (TT - 1 - t) : t;

            // stage x: warp w stages batch b=w (32 warps = 32 b)
            {
                int tok = text[w * TT + tt];
                float4 va = *(const float4*)(emb + tok*EE + lane*4);
                float4 vb = *(const float4*)(emb + tok*EE + (lane+32)*4);
                int ka = lane*4, kb = (lane+32)*4;
                xs_e[(ka+0)*33+w] = va.x; xs_e[(ka+1)*33+w] = va.y;
                xs_e[(ka+2)*33+w] = va.z; xs_e[(ka+3)*33+w] = va.w;
                xs_e[(kb+0)*33+w] = vb.x; xs_e[(kb+1)*33+w] = vb.y;
                xs_e[(kb+2)*33+w] = vb.z; xs_e[(kb+3)*33+w] = vb.w;
            }
            // stage h
            {
                const float4* s4 = (const float4*)g_henc[dir][p];
                for (int i2 = tid; i2 < 2048; i2 += NTHR) {
                    float4 v4 = __ldcg(s4 + i2);
                    int k = i2 >> 3, b4 = (i2 & 7) * 4;
                    hs_e[k*33+b4+0] = v4.x; hs_e[k*33+b4+1] = v4.y;
                    hs_e[k*33+b4+2] = v4.z; hs_e[k*33+b4+3] = v4.w;
                }
            }
            __syncthreads();

            // each warp: 4 gate rows x 128-k quarter, weights from smem
            {
                const float* xp = (part ? hs_e : xs_e) + qh*128*33;
                const float* wq = sm + EW_OFF + u_w*512 + part*256 + qh*128;
                float a0 = 0.f, a1 = 0.f, a2 = 0.f, a3 = 0.f;
                #pragma unroll 8
                for (int k = 0; k < 128; k += 4) {
                    float x0 = xp[(k+0)*33+lane], x1 = xp[(k+1)*33+lane];
                    float x2 = xp[(k+2)*33+lane], x3 = xp[(k+3)*33+lane];
                    float4 q;
                    q = *(const float4*)(wq + 0*4096 + k);
                    a0 += q.x*x0+q.y*x1+q.z*x2+q.w*x3;
                    q = *(const float4*)(wq + 1*4096 + k);
                    a1 += q.x*x0+q.y*x1+q.z*x2+q.w*x3;
                    q = *(const float4*)(wq + 2*4096 + k);
                    a2 += q.x*x0+q.y*x1+q.z*x2+q.w*x3;
                    q = *(const float4*)(wq + 3*4096 + k);
                    a3 += q.x*x0+q.y*x1+q.z*x2+q.w*x3;
                }
                pa[pq*1024 + (0*8+u_w)*32 + lane] = a0;
                pa[pq*1024 + (1*8+u_w)*32 + lane] = a1;
                pa[pq*1024 + (2*8+u_w)*32 + lane] = a2;
                pa[pq*1024 + (3*8+u_w)*32 + lane] = a3;
            }
            __syncthreads();
            // reduce 4 partials -> ga
            {
                int row = tid >> 5;
                ga[row*32 + lane] = pa[row*32+lane] + pa[1024+row*32+lane]
                                  + pa[2048+row*32+lane] + pa[3072+row*32+lane];
            }
            __syncthreads();
            // LSTM update: 256 threads = (u_l, b)
            if (tid < 256) {
                int u_l = tid >> 5, b = tid & 31;
                int u = bxx*8 + u_l;
                float gi = ga[(0*8+u_l)*32+b] + bias[0*HH+u];
                float gf = ga[(1*8+u_l)*32+b] + bias[1*HH+u];
                float gg = ga[(2*8+u_l)*32+b] + bias[2*HH+u];
                float go = ga[(3*8+u_l)*32+b] + bias[3*HH+u];
                float cc = g_cenc[dir][u*32 + b];
                float cn = sigf(gf) * cc + sigf(gi) * tanhx(gg);
                float hn = sigf(go) * tanhx(cn);
                g_cenc[dir][u*32 + b] = cn;
                g_henc[dir][1 - p][u*32 + b] = hn;
                g_enc_out[(b*TT + tt)*ENCX + dir*HH + u] = hn;
            }
            esync(dir);
        }
    }
    gsync();

    // ---------- proj_enc GEMM (512 active threads) ----------
    {
        float* As = sm;           // [16][65]
        float* Bs = sm + 1040;    // [16][65]
        const int tx = tid & 15, ty2 = tid >> 4;
        for (int tl = cta; tl < 1600; tl += NCTA) {
            const int n0 = (tl & 15) * 64, m0 = (tl >> 4) * 64;
            float acc[2][4];
            #pragma unroll
            for (int i = 0; i < 2; i++)
                #pragma unroll
                for (int j = 0; j < 4; j++) acc[i][j] = 0.f;
            for (int k0 = 0; k0 < ENCX; k0 += 16) {
                if (tid < 256) {
                    int rr = tid >> 2, q = tid & 3;
                    float4 a4 = *(const float4*)(g_enc_out + (m0 + rr)*ENCX + k0 + q*4);
                    As[(q*4+0)*65+rr] = a4.x; As[(q*4+1)*65+rr] = a4.y;
                    As[(q*4+2)*65+rr] = a4.z; As[(q*4+3)*65+rr] = a4.w;
                } else if (tid < 512) {
                    int t2 = tid - 256;
                    int rr = t2 >> 2, q = t2 & 3;
                    float4 b4 = *(const float4*)(Ws + (n0 + rr)*(ENCX+DECX) + k0 + q*4);
                    Bs[(q*4+0)*65+rr] = b4.x; Bs[(q*4+1)*65+rr] = b4.y;
                    Bs[(q*4+2)*65+rr] = b4.z; Bs[(q*4+3)*65+rr] = b4.w;
                }
                __syncthreads();
                if (tid < 512) {
                    #pragma unroll
                    for (int k = 0; k < 16; k++) {
                        float ar0 = As[k*65 + ty2*2 + 0];
                        float ar1 = As[k*65 + ty2*2 + 1];
                        float br[4];
                        #pragma unroll
                        for (int j = 0; j < 4; j++) br[j] = Bs[k*65 + tx*4 + j];
                        #pragma unroll
                        for (int j = 0; j < 4; j++) { acc[0][j] += ar0*br[j]; acc[1][j] += ar1*br[j]; }
                    }
                }
                __syncthreads();
            }
            if (tid < 512) {
                #pragma unroll
                for (int i = 0; i < 2; i++)
                    #pragma unroll
                    for (int j = 0; j < 4; j++)
                        g_proj[(m0 + ty2*2 + i)*DECX + n0 + tx*4 + j] = acc[i][j] + bs[n0 + tx*4 + j];
            }
        }
        __syncthreads();
    }

    // ---------- preload decoder gate weights + v ----------
    {
        for (int i = tid; i < 28*1616; i += NTHR) {
            int r = i / 1616, k = i - r*1616;
            int u = cta*7 + (r >> 2), g = r & 3;
            float val = 0.f;
            if (u < DECX)
                val = (k < 592) ? dWih[(g*DECX+u)*592 + k] : dWhh[(g*DECX+u)*DECX + (k-592)];
            sm[WS_OFF + i] = val;
        }
        for (int i = tid; i < DECX; i += NTHR) sm[V_OFF + i] = v[i];
        __syncthreads();
    }
    gsync();

    // ---------- decoder: 400 steps ----------
    float* xs0 = sm + XB0_OFF;
    float* xs1 = sm + XB1_OFF;
    const float* vs = sm + V_OFF;

    for (int t = 0; t < TM; t++) {
        const int p = t & 1;

        // --- A: scores; 128 CTAs = (b, 50-s chunk); hproj cached in smem ---
        if (cta < 128) {
            const int b = cta >> 2, sc0 = (cta & 3) * 50;
            float* hp = xs0;
            for (int i = tid; i < DECX; i += NTHR) hp[i] = __ldcg(g_hproj + b*DECX + i);
            __syncthreads();
            for (int si = w; si < 50; si += 32) {
                const int s = sc0 + si;
                const float* pr = g_proj + (b*TT + s)*DECX;
                float acc = 0.f;
                #pragma unroll 8
                for (int d = lane; d < DECX; d += 32)
                    acc += vs[d] * tanhx(pr[d] + hp[d]);
                #pragma unroll
                for (int o = 16; o; o >>= 1) acc += __shfl_xor_sync(0xffffffffu, acc, o);
                if (lane == 0) g_scores[b*TT + s] = acc;
            }
        }
        gsync();

        // --- B: softmax + context, 128 CTAs (b x 4 e-chunks) ---
        if (cta < 128) {
            const int b = cta >> 2, ec = cta & 3;
            float* wb  = xs0;          // [200]
            float* red = xs0 + 256;    // [32]
            float* pc  = xs0 + 288;    // [1024]
            float sc = (tid < TT) ? __ldcg(g_scores + b*TT + tid) : -1e30f;

            float m = sc;
            #pragma unroll
            for (int o = 16; o; o >>= 1) m = fmaxf(m, __shfl_xor_sync(0xffffffffu, m, o));
            if (lane == 0) red[w] = m;
            __syncthreads();
            m = red[0];
            #pragma unroll
            for (int i = 1; i < 32; i++) m = fmaxf(m, red[i]);
            __syncthreads();

            float e2 = (tid < TT) ? __expf(sc - m) : 0.f;
            float sum = e2;
            #pragma unroll
            for (int o = 16; o; o >>= 1) sum += __shfl_xor_sync(0xffffffffu, sum, o);
            if (lane == 0) red[w] = sum;
            __syncthreads();
            sum = red[0];
            #pragma unroll
            for (int i = 1; i < 32; i++) sum += red[i];

            float inv = __fdividef(1.f, sum);
            if (tid < TT) {
                float ww = e2 * inv; wb[tid] = ww;
                if (ec == 0) out[AOFF + (b*TM + t)*TT + tid] = ww;
            }
            __syncthreads();
            const int el = tid & 127, sq = tid >> 7;   // sq 0..7, 25 s each
            const int e = ec*128 + el;
            float c = 0.f;
            for (int s = sq*25; s < sq*25 + 25; s++)
                c += wb[s] * g_enc_out[(b*TT + s)*ENCX + e];
            pc[sq*128 + el] = c;
            __syncthreads();
            if (tid < 128) {
                float tot = 0.f;
                #pragma unroll
                for (int j = 0; j < 8; j++) tot += pc[j*128 + tid];
                g_ctx[b*ENCX + ec*128 + tid] = tot;
            }
        }
        gsync();

        // --- C: gates GEMM + LSTM; 8 act warps (2/SMSP), 24 staging warps ---
        {
            const int nr = (w < 4) ? 4 : 3;
            const int rb = (w < 4) ? w*4 : 16 + (w-4)*3;   // row base (w<8)
            const float* wsb = sm + WS_OFF + rb*1616;
            float acc[4] = {0.f, 0.f, 0.f, 0.f};

            // stage chunk 0 (mel) -> xs0 (all warps)
            for (int i = tid; i < 640; i += NTHR) {
                int b2 = i / 20, q = i % 20;
                float4 mv = (t == 0) ? make_float4(0.f,0.f,0.f,0.f)
                          : *(const float4*)(melt + (b2*TM + (t-1))*OUTX + q*4);
                *(float4*)(xs0 + b2*XSTR + q*4) = mv;
            }
            __syncthreads();

            for (int c = 0; c <= 12; c++) {
                if (w >= 8 && c < 12) {
                    float* nxt = (c & 1) ? xs0 : xs1;   // buffer for chunk c+1
                    const float* src = (c < 4) ? (g_ctx + c*128)
                                               : (g_hdec[p] + (c-4)*128);
                    const int stride = (c < 4) ? ENCX : DECX;
                    for (int i = (w-8)*32 + lane; i < 1024; i += 768) {
                        int b2 = i >> 5, q = i & 31;
                        float4 v4 = __ldcg((const float4*)(src + b2*stride + q*4));
                        *(float4*)(nxt + b2*XSTR + q*4) = v4;
                    }
                }
                if (w < 8) {
                    const float* cur = (c & 1) ? xs1 : xs0;
                    const int xo  = (c == 0) ? 0 : (OUTX + (c-1)*128);
                    const int len = (c == 0) ? OUTX : 128;
                    const float* xb = cur + lane*XSTR;
                    if (w < 4) gemv_rows<4>(wsb, xb, xo, len, acc);
                    else       gemv_rows<3>(wsb, xb, xo, len, acc);
                }
                __syncthreads();
            }
            float* ga = sm + GA_OFF;
            if (w < 8) {
                for (int i = 0; i < nr; i++) ga[(rb+i)*32 + lane] = acc[i];
            }
            __syncthreads();
            if (tid < 224) {
                int u_l = tid >> 5, b2 = tid & 31;
                int uu = cta*7 + u_l;
                if (uu < DECX) {
                    float gi = ga[(u_l*4+0)*32+b2] + db[0*DECX+uu];
                    float gf = ga[(u_l*4+1)*32+b2] + db[1*DECX+uu];
                    float gg = ga[(u_l*4+2)*32+b2] + db[2*DECX+uu];
                    float go = ga[(u_l*4+3)*32+b2] + db[3*DECX+uu];
                    float cc = g_cdec[uu*32+b2];
                    float cn = sigf(gf)*cc + sigf(gi)*tanhx(gg);
                    float hn = sigf(go)*tanhx(cn);
                    g_cdec[uu*32+b2] = cn;
                    g_hdec[1-p][b2*DECX + uu] = hn;
                }
            }
        }
        gsync();

        // --- D: hproj / mel / stop; 8 act warps x 1 row, 24 staging warps ---
        {
            const int r = cta*8 + w;   // valid for w<8
            const float* hsrc = g_hdec[1 - p];
            const float* wr = (r < DECX) ? (Ws + r*(ENCX+DECX) + ENCX)
                            : (r < DECX+OUTX) ? (Wout + (r-DECX)*DECX)
                            : Wstop;
            const bool dv = (w < 8) && (r <= DECX + OUTX);
            float d0 = 0.f;

            // stage chunk 0 (all warps)
            for (int i = tid; i < 1024; i += NTHR) {
                int b2 = i >> 5, q = i & 31;
                *(float4*)(xs0 + b2*XSTR + q*4) = __ldcg((const float4*)(hsrc + b2*DECX + q*4));
            }
            __syncthreads();

            for (int c = 0; c < 8; c++) {
                if (w >= 8 && c < 7) {
                    float* nxt = (c & 1) ? xs0 : xs1;
                    for (int i = (w-8)*32 + lane; i < 1024; i += 768) {
                        int b2 = i >> 5, q = i & 31;
                        *(float4*)(nxt + b2*XSTR + q*4) =
                            __ldcg((const float4*)(hsrc + b2*DECX + (c+1)*128 + q*4));
                    }
                }
                if (dv) {
                    const float* cur = (c & 1) ? xs1 : xs0;
                    const float* xb = cur + lane*XSTR;
                    const int ko = c*128;
                    #pragma unroll 8
                    for (int k = 0; k < 128; k += 4) {
                        float4 xv = *(const float4*)(xb + k);
                        float4 q0 = *(const float4*)(wr + ko + k);
                        d0 += q0.x*xv.x + q0.y*xv.y + q0.z*xv.z + q0.w*xv.w;
                    }
                }
                __syncthreads();
            }
            if (dv) {
                if (r < DECX) g_hproj[lane*DECX + r] = d0;
                else if (r < DECX+OUTX) out[(lane*TM + t)*OUTX + (r-DECX)] = d0 + bout[r-DECX];
                else out[SOFF + lane*TM + t] = sigf(d0 + bstop[0]);
            }
        }
        gsync();
    }
}

extern "C" void kernel_launch(void* const* d_in, const int* in_sizes, int n_in,
                              void* d_out, int out_size)
{
    const int*   text  = (const int*)d_in[0];
    const float* melt  = (const float*)d_in[1];
    const float* emb   = (const float*)d_in[2];
    const float* efWih = (const float*)d_in[3];
    const float* efWhh = (const float*)d_in[4];
    const float* efb   = (const float*)d_in[5];
    const float* ebWih = (const float*)d_in[6];
    const float* ebWhh = (const float*)d_in[7];
    const float* ebb   = (const float*)d_in[8];
    const float* Ws    = (const float*)d_in[9];
    const float* bs    = (const float*)d_in[10];
    const float* v     = (const float*)d_in[11];
    const float* dWih  = (const float*)d_in[12];
    const float* dWhh  = (const float*)d_in[13];
    const float* db    = (const float*)d_in[14];
    const float* Wout  = (const float*)d_in[15];
    const float* bout  = (const float*)d_in[16];
    const float* Wstop = (const float*)d_in[17];
    const float* bstop = (const float*)d_in[18];
    float* out = (float*)d_out;

    static int smem_set = 0;
    if (!smem_set) {
        cudaFuncSetAttribute(k_mega, cudaFuncAttributeMaxDynamicSharedMemorySize, SMEM_BYTES);
        smem_set = 1;
    }
    k_mega<<<NCTA, NTHR, SMEM_BYTES>>>(text, melt, emb, efWih, efWhh, efb,
                                       ebWih, ebWhh, ebb, Ws, bs, v,
                                       dWih, dWhh, db, Wout, bout, Wstop, bstop, out);
}